// round 1
// baseline (speedup 1.0000x reference)
#include <cuda_runtime.h>
#include <math.h>

// ---------------------------------------------------------------------------
// SambaMixerBlock: B=8, S=D=1024, N=16, DCONV=4, EXPAND=2 -> DI=2048, DT_RANK=64
// Both mamba blocks are (B, L=1024, dm=1024) -> identical shapes/buffers.
// ---------------------------------------------------------------------------

#define BSZ   8
#define SEQ   1024
#define DM    1024
#define DI_   2048
#define NST   16
#define DTR   64
#define XD    96          // DTR + 2*NST
#define ROWS  (BSZ*SEQ)   // 8192 GEMM rows

// scratch (device globals; allocation-free rule)
__device__ float g_xz  [(size_t)ROWS * 2 * DI_];  // 134 MB  (xh_pre | z)
__device__ float g_xh  [(size_t)ROWS * DI_];      // 67 MB
__device__ float g_dt  [(size_t)ROWS * DI_];
__device__ float g_y   [(size_t)ROWS * DI_];
__device__ float g_xdbl[(size_t)ROWS * XD];
__device__ float g_res1[(size_t)ROWS * DM];
__device__ float g_hmix[(size_t)ROWS * DM];
__device__ float g_hmixT[(size_t)ROWS * DM];
__device__ float g_outm[(size_t)ROWS * DM];

// ---------------------------------------------------------------------------
// Tiled SGEMM:  C[M,N] = A[M,K(lda)] * B[N,K]^T   (+ optional softplus(bias) epi)
// 128x128 block tile, BK=8, 256 threads, 8x8 per thread.
// ---------------------------------------------------------------------------
__global__ __launch_bounds__(256) void sgemm_abT(
    const float* __restrict__ A, int lda,
    const float* __restrict__ Bm,         // (N, K) row-major
    const float* __restrict__ bias,       // per-col, used when epi==1
    float* __restrict__ C,
    int M, int N, int K, int epi)
{
    __shared__ __align__(16) float As[8][128];
    __shared__ __align__(16) float Bs[8][128];

    const int tid  = threadIdx.x;
    const int bm   = blockIdx.y * 128;
    const int bn   = blockIdx.x * 128;
    const int lrow = tid >> 1;            // 0..127
    const int lcol = (tid & 1) * 4;       // 0 or 4
    const int tr   = tid >> 4;            // 0..15
    const int tc   = tid & 15;            // 0..15

    float acc[8][8];
#pragma unroll
    for (int i = 0; i < 8; i++)
#pragma unroll
        for (int j = 0; j < 8; j++) acc[i][j] = 0.f;

    const float* Ap = A + (size_t)(bm + lrow) * lda + lcol;
    const bool  bok = (bn + lrow) < N;
    const float* Bp = Bm + (size_t)(bn + lrow) * K + lcol;

    for (int k0 = 0; k0 < K; k0 += 8) {
        float4 av = *(const float4*)(Ap + k0);
        float4 bv = make_float4(0.f, 0.f, 0.f, 0.f);
        if (bok) bv = *(const float4*)(Bp + k0);

        As[lcol + 0][lrow] = av.x; As[lcol + 1][lrow] = av.y;
        As[lcol + 2][lrow] = av.z; As[lcol + 3][lrow] = av.w;
        Bs[lcol + 0][lrow] = bv.x; Bs[lcol + 1][lrow] = bv.y;
        Bs[lcol + 2][lrow] = bv.z; Bs[lcol + 3][lrow] = bv.w;
        __syncthreads();

#pragma unroll
        for (int kk = 0; kk < 8; kk++) {
            float ra[8], rb[8];
            *(float4*)(ra)     = *(const float4*)&As[kk][tr * 8];
            *(float4*)(ra + 4) = *(const float4*)&As[kk][tr * 8 + 4];
            *(float4*)(rb)     = *(const float4*)&Bs[kk][tc * 8];
            *(float4*)(rb + 4) = *(const float4*)&Bs[kk][tc * 8 + 4];
#pragma unroll
            for (int i = 0; i < 8; i++)
#pragma unroll
                for (int j = 0; j < 8; j++) acc[i][j] += ra[i] * rb[j];
        }
        __syncthreads();
    }

#pragma unroll
    for (int i = 0; i < 8; i++) {
        const int row = bm + tr * 8 + i;
        float* crow = C + (size_t)row * N;
#pragma unroll
        for (int j = 0; j < 8; j++) {
            const int col = bn + tc * 8 + j;
            if (col < N) {
                float v = acc[i][j];
                if (epi == 1) {                       // softplus(v + bias)
                    v += bias[col];
                    v = (v > 20.f) ? v : log1pf(__expf(v));
                }
                crow[col] = v;
            }
        }
    }
}

// ---------------------------------------------------------------------------
// Depthwise causal conv (DCONV=4) + bias + SiLU.  Reads xh_pre = xz[:, :, :DI].
// ---------------------------------------------------------------------------
__global__ __launch_bounds__(256) void conv_silu_kernel(
    const float* __restrict__ xz, const float* __restrict__ w,
    const float* __restrict__ bias, float* __restrict__ xh)
{
    const long i = (long)blockIdx.x * 256 + threadIdx.x;   // over (b,l,d)
    const int  d = (int)(i & (DI_ - 1));
    const long bl = i >> 11;
    const int  l = (int)(bl & (SEQ - 1));
    const long b = bl >> 10;

    const float* base = xz + ((size_t)b * SEQ) * (2 * DI_) + d;
    float acc = bias[d];
    const float w0 = w[d * 4 + 0], w1 = w[d * 4 + 1], w2 = w[d * 4 + 2], w3 = w[d * 4 + 3];
    if (l >= 3) acc += w0 * base[(size_t)(l - 3) * (2 * DI_)];
    if (l >= 2) acc += w1 * base[(size_t)(l - 2) * (2 * DI_)];
    if (l >= 1) acc += w2 * base[(size_t)(l - 1) * (2 * DI_)];
    acc += w3 * base[(size_t)l * (2 * DI_)];
    xh[i] = acc / (1.f + __expf(-acc));                    // silu
}

// ---------------------------------------------------------------------------
// Selective scan: thread = (b, d). 16 states in registers, B/C staged in smem.
// Fused: y = (scan + x*D) * silu(z)
// ---------------------------------------------------------------------------
__global__ __launch_bounds__(128) void scan_kernel(
    const float* __restrict__ dtb, const float* __restrict__ xh,
    const float* __restrict__ xdbl,                         // B at +DTR, C at +DTR+NST
    const float* __restrict__ xz,                           // z at col DI_
    const float* __restrict__ A_log, const float* __restrict__ Dp,
    float* __restrict__ y)
{
    const int b = blockIdx.y;
    const int d = blockIdx.x * 128 + threadIdx.x;

    float A[NST], h[NST];
#pragma unroll
    for (int n = 0; n < NST; n++) {
        A[n] = -__expf(A_log[d * NST + n]);
        h[n] = 0.f;
    }
    const float dval = Dp[d];

    __shared__ float sB[NST], sC[NST];
    const size_t rowbase = (size_t)b * SEQ;

    for (int l = 0; l < SEQ; l++) {
        __syncthreads();
        if (threadIdx.x < 2 * NST) {
            float v = xdbl[(rowbase + l) * XD + DTR + threadIdx.x];
            if (threadIdx.x < NST) sB[threadIdx.x] = v;
            else                   sC[threadIdx.x - NST] = v;
        }
        __syncthreads();

        const size_t idx = (rowbase + l) * DI_ + d;
        const float dt = dtb[idx];
        const float x  = xh[idx];
        const float z  = xz[(rowbase + l) * (2 * DI_) + DI_ + d];
        const float dx = dt * x;
        float acc = 0.f;
#pragma unroll
        for (int n = 0; n < NST; n++) {
            h[n] = __expf(dt * A[n]) * h[n] + dx * sB[n];
            acc += h[n] * sC[n];
        }
        acc += x * dval;
        acc *= z / (1.f + __expf(-z));                    // * silu(z)
        y[idx] = acc;
    }
}

// ---------------------------------------------------------------------------
// block-wide sum (256 threads)
// ---------------------------------------------------------------------------
__device__ __forceinline__ float block_sum256(float v)
{
    __shared__ float red[8];
    const int lane = threadIdx.x & 31, w = threadIdx.x >> 5;
#pragma unroll
    for (int o = 16; o; o >>= 1) v += __shfl_xor_sync(0xffffffffu, v, o);
    if (!lane) red[w] = v;
    __syncthreads();
    if (w == 0) {
        v = (lane < 8) ? red[lane] : 0.f;
#pragma unroll
        for (int o = 4; o; o >>= 1) v += __shfl_xor_sync(0xffffffffu, v, o);
        if (!lane) red[0] = v;
    }
    __syncthreads();
    return red[0];
}

// ---------------------------------------------------------------------------
// res1 = residual + hscm[:,1]; rmsnorm; mix [hstm0, hstm1, hscm0, hnorm]
// ---------------------------------------------------------------------------
__global__ __launch_bounds__(256) void rms_mix_tm_kernel(
    const float* __restrict__ residual, const float* __restrict__ hstm,
    const float* __restrict__ hscm, const float* __restrict__ nw,
    const float* __restrict__ wavg, float* __restrict__ res1, float* __restrict__ hmix)
{
    const int bs = blockIdx.x, b = bs >> 10, s = bs & 1023, t = threadIdx.x;
    const size_t r4 = (size_t)bs * 256 + t;
    const size_t i0 = ((size_t)(b * 2 + 0) * 1024 + s) * 256 + t;
    const size_t i1 = ((size_t)(b * 2 + 1) * 1024 + s) * 256 + t;

    float4 r  = ((const float4*)residual)[r4];
    float4 c1 = ((const float4*)hscm)[i1];
    r.x += c1.x; r.y += c1.y; r.z += c1.z; r.w += c1.w;
    ((float4*)res1)[r4] = r;

    const float tot = block_sum256(r.x * r.x + r.y * r.y + r.z * r.z + r.w * r.w);
    const float scale = rsqrtf(tot * (1.f / (float)DM) + 1e-5f);

    float w0 = wavg[s], w1 = wavg[1024 + s], w2 = wavg[2048 + s], w3 = wavg[3072 + s];
    const float mx = fmaxf(fmaxf(w0, w1), fmaxf(w2, w3));
    w0 = __expf(w0 - mx); w1 = __expf(w1 - mx); w2 = __expf(w2 - mx); w3 = __expf(w3 - mx);
    const float inv = 1.f / (w0 + w1 + w2 + w3);
    w0 *= inv; w1 *= inv; w2 *= inv; w3 *= inv;

    const float4 a0 = ((const float4*)hstm)[i0];
    const float4 a1 = ((const float4*)hstm)[i1];
    const float4 c0 = ((const float4*)hscm)[i0];
    const float4 wn = ((const float4*)nw)[t];
    float4 o;
    o.x = w0 * a0.x + w1 * a1.x + w2 * c0.x + w3 * (r.x * scale * wn.x);
    o.y = w0 * a0.y + w1 * a1.y + w2 * c0.y + w3 * (r.y * scale * wn.y);
    o.z = w0 * a0.z + w1 * a1.z + w2 * c0.z + w3 * (r.z * scale * wn.z);
    o.w = w0 * a0.w + w1 * a1.w + w2 * c0.w + w3 * (r.w * scale * wn.w);
    ((float4*)hmix)[r4] = o;
}

// ---------------------------------------------------------------------------
// res2 = res1 + out_tm; rmsnorm; mix [hstm0, hstm1, hnorm, hscm0, hscm1]
// ---------------------------------------------------------------------------
__global__ __launch_bounds__(256) void rms_mix_cm_kernel(
    const float* __restrict__ res1, const float* __restrict__ outm,
    const float* __restrict__ hstm, const float* __restrict__ hscm,
    const float* __restrict__ nw, const float* __restrict__ wavg,
    float* __restrict__ res2, float* __restrict__ hmix)
{
    const int bs = blockIdx.x, b = bs >> 10, s = bs & 1023, t = threadIdx.x;
    const size_t r4 = (size_t)bs * 256 + t;
    const size_t i0 = ((size_t)(b * 2 + 0) * 1024 + s) * 256 + t;
    const size_t i1 = ((size_t)(b * 2 + 1) * 1024 + s) * 256 + t;

    float4 r  = ((const float4*)res1)[r4];
    float4 om = ((const float4*)outm)[r4];
    r.x += om.x; r.y += om.y; r.z += om.z; r.w += om.w;
    ((float4*)res2)[r4] = r;

    const float tot = block_sum256(r.x * r.x + r.y * r.y + r.z * r.z + r.w * r.w);
    const float scale = rsqrtf(tot * (1.f / (float)DM) + 1e-5f);

    float w[5];
#pragma unroll
    for (int n = 0; n < 5; n++) w[n] = wavg[n * 1024 + s];
    float mx = w[0];
#pragma unroll
    for (int n = 1; n < 5; n++) mx = fmaxf(mx, w[n]);
    float sum = 0.f;
#pragma unroll
    for (int n = 0; n < 5; n++) { w[n] = __expf(w[n] - mx); sum += w[n]; }
    const float inv = 1.f / sum;
#pragma unroll
    for (int n = 0; n < 5; n++) w[n] *= inv;

    const float4 a0 = ((const float4*)hstm)[i0];
    const float4 a1 = ((const float4*)hstm)[i1];
    const float4 c0 = ((const float4*)hscm)[i0];
    const float4 c1 = ((const float4*)hscm)[i1];
    const float4 wn = ((const float4*)nw)[t];
    float4 o;
    o.x = w[0]*a0.x + w[1]*a1.x + w[2]*(r.x*scale*wn.x) + w[3]*c0.x + w[4]*c1.x;
    o.y = w[0]*a0.y + w[1]*a1.y + w[2]*(r.y*scale*wn.y) + w[3]*c0.y + w[4]*c1.y;
    o.z = w[0]*a0.z + w[1]*a1.z + w[2]*(r.z*scale*wn.z) + w[3]*c0.z + w[4]*c1.z;
    o.w = w[0]*a0.w + w[1]*a1.w + w[2]*(r.w*scale*wn.w) + w[3]*c0.w + w[4]*c1.w;
    ((float4*)hmix)[r4] = o;
}

// ---------------------------------------------------------------------------
// Batched 1024x1024 transpose (out[b,c,r] = in[b,r,c])
// ---------------------------------------------------------------------------
__global__ __launch_bounds__(256) void transpose_kernel(
    const float* __restrict__ in, float* __restrict__ out)
{
    __shared__ float tile[32][33];
    const int b = blockIdx.z;
    const int r0 = blockIdx.y * 32, c0 = blockIdx.x * 32;
    const size_t base = (size_t)b * 1024 * 1024;
#pragma unroll
    for (int i = threadIdx.y; i < 32; i += 8)
        tile[i][threadIdx.x] = in[base + (size_t)(r0 + i) * 1024 + c0 + threadIdx.x];
    __syncthreads();
#pragma unroll
    for (int i = threadIdx.y; i < 32; i += 8)
        out[base + (size_t)(c0 + i) * 1024 + r0 + threadIdx.x] = tile[threadIdx.x][i];
}

// ---------------------------------------------------------------------------
// host side
// ---------------------------------------------------------------------------
static void run_mamba(const float* x, const float* const* P, float* out,
                      float* xz, float* xh, float* dtb, float* yb, float* xdbl)
{
    const float* in_w   = P[0];
    const float* conv_w = P[1];
    const float* conv_b = P[2];
    const float* xproj  = P[3];
    const float* dt_w   = P[4];
    const float* dt_b   = P[5];
    const float* A_log  = P[6];
    const float* Dp     = P[7];
    const float* out_w  = P[8];

    sgemm_abT<<<dim3(2 * DI_ / 128, ROWS / 128), 256>>>(x, DM, in_w, nullptr, xz,
                                                        ROWS, 2 * DI_, DM, 0);
    conv_silu_kernel<<<(ROWS * DI_) / 256, 256>>>(xz, conv_w, conv_b, xh);
    sgemm_abT<<<dim3(1, ROWS / 128), 256>>>(xh, DI_, xproj, nullptr, xdbl,
                                            ROWS, XD, DI_, 0);
    sgemm_abT<<<dim3(DI_ / 128, ROWS / 128), 256>>>(xdbl, XD, dt_w, dt_b, dtb,
                                                    ROWS, DI_, DTR, 1);
    scan_kernel<<<dim3(DI_ / 128, BSZ), 128>>>(dtb, xh, xdbl, xz, A_log, Dp, yb);
    sgemm_abT<<<dim3(DM / 128, ROWS / 128), 256>>>(yb, DI_, out_w, nullptr, out,
                                                   ROWS, DM, DI_, 0);
}

extern "C" void kernel_launch(void* const* d_in, const int* in_sizes, int n_in,
                              void* d_out, int out_size)
{
    const float* hstm     = (const float*)d_in[0];
    const float* hscm     = (const float*)d_in[1];
    const float* residual = (const float*)d_in[2];
    const float* norm_tm  = (const float*)d_in[3];
    const float* wavg_tm  = (const float*)d_in[4];

    // Input ordering: setup_inputs() dict order puts norm_cm_w (1024 elems) at
    // index 5; reference-signature order puts tm_in_w (4.19M elems) there.
    const float *norm_cm, *wavg_cm;
    int btm;
    const int bcm = 16;
    if (in_sizes[5] == 1024) {            // dict order
        norm_cm = (const float*)d_in[5];
        wavg_cm = (const float*)d_in[6];
        btm = 7;
    } else {                              // signature order
        btm = 5;
        norm_cm = (const float*)d_in[14];
        wavg_cm = (const float*)d_in[15];
    }
    const float* P_tm[9];
    const float* P_cm[9];
    for (int i = 0; i < 9; i++) {
        P_tm[i] = (const float*)d_in[btm + i];
        P_cm[i] = (const float*)d_in[bcm + i];
    }

    float *xz, *xh, *dtb, *yb, *xdbl, *res1, *hmix, *hmixT, *outm;
    cudaGetSymbolAddress((void**)&xz,    g_xz);
    cudaGetSymbolAddress((void**)&xh,    g_xh);
    cudaGetSymbolAddress((void**)&dtb,   g_dt);
    cudaGetSymbolAddress((void**)&yb,    g_y);
    cudaGetSymbolAddress((void**)&xdbl,  g_xdbl);
    cudaGetSymbolAddress((void**)&res1,  g_res1);
    cudaGetSymbolAddress((void**)&hmix,  g_hmix);
    cudaGetSymbolAddress((void**)&hmixT, g_hmixT);
    cudaGetSymbolAddress((void**)&outm,  g_outm);

    float* dout = (float*)d_out;
    const long total = (long)BSZ * SEQ * DM;             // 8388608 per tensor
    float* res2_out = (out_size >= 2 * total) ? (dout + total) : res1;

    // --- token-mixer path ---
    rms_mix_tm_kernel<<<ROWS, 256>>>(residual, hstm, hscm, norm_tm, wavg_tm, res1, hmix);
    run_mamba(hmix, P_tm, outm, xz, xh, dtb, yb, xdbl);

    // --- channel-mixer path ---
    rms_mix_cm_kernel<<<ROWS, 256>>>(res1, outm, hstm, hscm, norm_cm, wavg_cm, res2_out, hmix);
    transpose_kernel<<<dim3(32, 32, BSZ), dim3(32, 8)>>>(hmix, hmixT);
    run_mamba(hmixT, P_cm, outm, xz, xh, dtb, yb, xdbl);
    transpose_kernel<<<dim3(32, 32, BSZ), dim3(32, 8)>>>(outm, dout);
}

// round 3
// speedup vs baseline: 1.9469x; 1.9469x over previous
#include <cuda_runtime.h>
#include <cuda_fp16.h>
#include <cstdint>
#include <math.h>

// ---------------------------------------------------------------------------
// SambaMixerBlock: B=8, S=D=1024, N=16, DCONV=4, EXPAND=2 -> DI=2048, DT_RANK=64
// Round 3: GEMMs on HMMA (mma.sync m16n8k16, fp16 hi/lo x3 split, fp32 acc).
// (tcgen05 PTX rejected: harness compiles for family-generic sm_103.)
// ---------------------------------------------------------------------------

#define BSZ   8
#define SEQ   1024
#define DM    1024
#define DI_   2048
#define NST   16
#define DTR   64
#define XD    96          // DTR + 2*NST
#define ROWS  (BSZ*SEQ)   // 8192 GEMM rows

// scratch (device globals; allocation-free rule)
__device__ float g_xz  [(size_t)ROWS * 2 * DI_];
__device__ float g_xh  [(size_t)ROWS * DI_];
__device__ float g_dt  [(size_t)ROWS * DI_];
__device__ float g_y   [(size_t)ROWS * DI_];
__device__ float g_xdbl[(size_t)ROWS * XD];
__device__ float g_res1[(size_t)ROWS * DM];
__device__ float g_hmix[(size_t)ROWS * DM];
__device__ float g_hmixT[(size_t)ROWS * DM];
__device__ float g_outm[(size_t)ROWS * DM];

// ---------------------------------------------------------------------------
// HMMA GEMM:  C[M,Nsz] = A[M,K(lda)] * B[Nsz,K]^T, fp16x3 split, fp32 acc.
// CTA tile 128x256, 8 warps (2x4), warp tile 64x64, BK=32, double-buffered.
// smem rows padded to 80B -> conflict-free fragment LDS.
// EPI==1: C = softplus(C + bias)
// ---------------------------------------------------------------------------
#define RS      80                       // smem row stride (bytes), 32 cols fp16 + pad
#define OFF_AL  10240                    // 128*80
#define OFF_BH  20480
#define OFF_BL  40960
#define STAGE_B 61440                    // bytes per stage
#define SMEM_T  (2 * STAGE_B)            // 122880

__device__ __forceinline__ void mma16816(float* d, const uint32_t* a, const uint32_t* b)
{
    asm volatile(
        "mma.sync.aligned.m16n8k16.row.col.f32.f16.f16.f32 "
        "{%0,%1,%2,%3}, {%4,%5,%6,%7}, {%8,%9}, {%0,%1,%2,%3};"
        : "+f"(d[0]), "+f"(d[1]), "+f"(d[2]), "+f"(d[3])
        : "r"(a[0]), "r"(a[1]), "r"(a[2]), "r"(a[3]), "r"(b[0]), "r"(b[1]));
}

template<int EPI>
__global__ __launch_bounds__(256, 1) void gemm_mma(
    const float* __restrict__ A, int lda,
    const float* __restrict__ Bm,            // (Nsz, K) row-major
    const float* __restrict__ bias,
    float* __restrict__ C,
    int M, int Nsz, int K)
{
    extern __shared__ __align__(16) char smem[];

    const int tid = threadIdx.x;
    const int wid = tid >> 5;
    const int lid = tid & 31;
    const int bm  = blockIdx.y * 128;
    const int bn  = blockIdx.x * 256;
    const int wm  = (wid & 1) * 64;
    const int wn  = (wid >> 1) * 64;
    const int g   = lid >> 2;             // groupID (row within 8)
    const int t4  = lid & 3;              // thread-in-group

    float acc[4][8][4];
#pragma unroll
    for (int i = 0; i < 4; i++)
#pragma unroll
        for (int j = 0; j < 8; j++)
#pragma unroll
            for (int c = 0; c < 4; c++) acc[i][j][c] = 0.f;

    const int S = K >> 5;                 // stages of BK=32

    for (int s = 0; s < S; s++) {
        char* sb = smem + (s & 1) * STAGE_B;
        const int k0 = s << 5;

        // ---- fill A: 128 rows x 32 cols fp32 -> hi/lo fp16 (1024 float4) ----
#pragma unroll
        for (int i = 0; i < 4; i++) {
            const int t   = tid + i * 256;
            const int row = t >> 3, c4 = t & 7;
            float4 v = *(const float4*)(A + (size_t)(bm + row) * lda + k0 + c4 * 4);
            __half2 h0 = __floats2half2_rn(v.x, v.y);
            float2  f0 = __half22float2(h0);
            __half2 l0 = __floats2half2_rn(v.x - f0.x, v.y - f0.y);
            __half2 h1 = __floats2half2_rn(v.z, v.w);
            float2  f1 = __half22float2(h1);
            __half2 l1 = __floats2half2_rn(v.z - f1.x, v.w - f1.y);
            char* p = sb + row * RS + c4 * 8;
            *(__half2*)(p)                = h0;
            *(__half2*)(p + 4)            = h1;
            *(__half2*)(p + OFF_AL)       = l0;
            *(__half2*)(p + OFF_AL + 4)   = l1;
        }
        // ---- fill B: 256 rows x 32 cols (2048 float4) ----
#pragma unroll
        for (int i = 0; i < 8; i++) {
            const int t   = tid + i * 256;
            const int row = t >> 3, c4 = t & 7;
            float4 v = make_float4(0.f, 0.f, 0.f, 0.f);
            if (bn + row < Nsz)
                v = *(const float4*)(Bm + (size_t)(bn + row) * K + k0 + c4 * 4);
            __half2 h0 = __floats2half2_rn(v.x, v.y);
            float2  f0 = __half22float2(h0);
            __half2 l0 = __floats2half2_rn(v.x - f0.x, v.y - f0.y);
            __half2 h1 = __floats2half2_rn(v.z, v.w);
            float2  f1 = __half22float2(h1);
            __half2 l1 = __floats2half2_rn(v.z - f1.x, v.w - f1.y);
            char* p = sb + OFF_BH + row * RS + c4 * 8;
            *(__half2*)(p)                        = h0;
            *(__half2*)(p + 4)                    = h1;
            *(__half2*)(p + OFF_BL - OFF_BH)      = l0;
            *(__half2*)(p + OFF_BL - OFF_BH + 4)  = l1;
        }
        __syncthreads();

        // ---- compute: two k16 steps ----
#pragma unroll
        for (int kk = 0; kk < 2; kk++) {
            const int cb = kk * 32 + t4 * 4;          // byte col offset
            uint32_t ah[4][4], al[4][4];
#pragma unroll
            for (int i = 0; i < 4; i++) {
                const char* pa = sb + (wm + i * 16 + g) * RS + cb;
                ah[i][0] = *(const uint32_t*)(pa);
                ah[i][1] = *(const uint32_t*)(pa + 8 * RS);
                ah[i][2] = *(const uint32_t*)(pa + 16);
                ah[i][3] = *(const uint32_t*)(pa + 8 * RS + 16);
                const char* pl = pa + OFF_AL;
                al[i][0] = *(const uint32_t*)(pl);
                al[i][1] = *(const uint32_t*)(pl + 8 * RS);
                al[i][2] = *(const uint32_t*)(pl + 16);
                al[i][3] = *(const uint32_t*)(pl + 8 * RS + 16);
            }
#pragma unroll
            for (int j = 0; j < 8; j++) {
                const char* pb = sb + OFF_BH + (wn + j * 8 + g) * RS + cb;
                uint32_t bh[2], bl[2];
                bh[0] = *(const uint32_t*)(pb);
                bh[1] = *(const uint32_t*)(pb + 16);
                bl[0] = *(const uint32_t*)(pb + (OFF_BL - OFF_BH));
                bl[1] = *(const uint32_t*)(pb + (OFF_BL - OFF_BH) + 16);
#pragma unroll
                for (int i = 0; i < 4; i++) {
                    mma16816(acc[i][j], ah[i], bh);
                    mma16816(acc[i][j], al[i], bh);
                    mma16816(acc[i][j], ah[i], bl);
                }
            }
        }
        __syncthreads();
    }

    // ---- epilogue: direct float2 stores ----
#pragma unroll
    for (int i = 0; i < 4; i++) {
        const int r0 = bm + wm + i * 16 + g;
#pragma unroll
        for (int j = 0; j < 8; j++) {
            const int c = bn + wn + j * 8 + t4 * 2;
            if (c < Nsz) {
                float v0 = acc[i][j][0], v1 = acc[i][j][1];
                float v2 = acc[i][j][2], v3 = acc[i][j][3];
                if (EPI == 1) {
                    const float b0 = bias[c], b1 = bias[c + 1];
                    v0 += b0; v1 += b1; v2 += b0; v3 += b1;
                    v0 = (v0 > 20.f) ? v0 : log1pf(__expf(v0));
                    v1 = (v1 > 20.f) ? v1 : log1pf(__expf(v1));
                    v2 = (v2 > 20.f) ? v2 : log1pf(__expf(v2));
                    v3 = (v3 > 20.f) ? v3 : log1pf(__expf(v3));
                }
                *(float2*)(C + (size_t)r0 * Nsz + c)       = make_float2(v0, v1);
                *(float2*)(C + (size_t)(r0 + 8) * Nsz + c) = make_float2(v2, v3);
            }
        }
    }
}

// ---------------------------------------------------------------------------
// Depthwise causal conv (DCONV=4) + bias + SiLU.
// ---------------------------------------------------------------------------
__global__ __launch_bounds__(256) void conv_silu_kernel(
    const float* __restrict__ xz, const float* __restrict__ w,
    const float* __restrict__ bias, float* __restrict__ xh)
{
    const long i = (long)blockIdx.x * 256 + threadIdx.x;
    const int  d = (int)(i & (DI_ - 1));
    const long bl = i >> 11;
    const int  l = (int)(bl & (SEQ - 1));
    const long b = bl >> 10;

    const float* base = xz + ((size_t)b * SEQ) * (2 * DI_) + d;
    float acc = bias[d];
    const float w0 = w[d * 4 + 0], w1 = w[d * 4 + 1], w2 = w[d * 4 + 2], w3 = w[d * 4 + 3];
    if (l >= 3) acc += w0 * base[(size_t)(l - 3) * (2 * DI_)];
    if (l >= 2) acc += w1 * base[(size_t)(l - 2) * (2 * DI_)];
    if (l >= 1) acc += w2 * base[(size_t)(l - 1) * (2 * DI_)];
    acc += w3 * base[(size_t)l * (2 * DI_)];
    xh[i] = acc / (1.f + __expf(-acc));
}

// ---------------------------------------------------------------------------
// Selective scan (fused D-skip and silu(z) gate)
// ---------------------------------------------------------------------------
__global__ __launch_bounds__(128) void scan_kernel(
    const float* __restrict__ dtb, const float* __restrict__ xh,
    const float* __restrict__ xdbl,
    const float* __restrict__ xz,
    const float* __restrict__ A_log, const float* __restrict__ Dp,
    float* __restrict__ y)
{
    const int b = blockIdx.y;
    const int d = blockIdx.x * 128 + threadIdx.x;

    float A[NST], h[NST];
#pragma unroll
    for (int n = 0; n < NST; n++) {
        A[n] = -__expf(A_log[d * NST + n]);
        h[n] = 0.f;
    }
    const float dval = Dp[d];

    __shared__ float sB[NST], sC[NST];
    const size_t rowbase = (size_t)b * SEQ;

    for (int l = 0; l < SEQ; l++) {
        __syncthreads();
        if (threadIdx.x < 2 * NST) {
            float v = xdbl[(rowbase + l) * XD + DTR + threadIdx.x];
            if (threadIdx.x < NST) sB[threadIdx.x] = v;
            else                   sC[threadIdx.x - NST] = v;
        }
        __syncthreads();

        const size_t idx = (rowbase + l) * DI_ + d;
        const float dt = dtb[idx];
        const float x  = xh[idx];
        const float z  = xz[(rowbase + l) * (2 * DI_) + DI_ + d];
        const float dx = dt * x;
        float acc = 0.f;
#pragma unroll
        for (int n = 0; n < NST; n++) {
            h[n] = __expf(dt * A[n]) * h[n] + dx * sB[n];
            acc += h[n] * sC[n];
        }
        acc += x * dval;
        acc *= z / (1.f + __expf(-z));
        y[idx] = acc;
    }
}

// ---------------------------------------------------------------------------
__device__ __forceinline__ float block_sum256(float v)
{
    __shared__ float red[8];
    const int lane = threadIdx.x & 31, w = threadIdx.x >> 5;
#pragma unroll
    for (int o = 16; o; o >>= 1) v += __shfl_xor_sync(0xffffffffu, v, o);
    if (!lane) red[w] = v;
    __syncthreads();
    if (w == 0) {
        v = (lane < 8) ? red[lane] : 0.f;
#pragma unroll
        for (int o = 4; o; o >>= 1) v += __shfl_xor_sync(0xffffffffu, v, o);
        if (!lane) red[0] = v;
    }
    __syncthreads();
    return red[0];
}

__global__ __launch_bounds__(256) void rms_mix_tm_kernel(
    const float* __restrict__ residual, const float* __restrict__ hstm,
    const float* __restrict__ hscm, const float* __restrict__ nw,
    const float* __restrict__ wavg, float* __restrict__ res1, float* __restrict__ hmix)
{
    const int bs = blockIdx.x, b = bs >> 10, s = bs & 1023, t = threadIdx.x;
    const size_t r4 = (size_t)bs * 256 + t;
    const size_t i0 = ((size_t)(b * 2 + 0) * 1024 + s) * 256 + t;
    const size_t i1 = ((size_t)(b * 2 + 1) * 1024 + s) * 256 + t;

    float4 r  = ((const float4*)residual)[r4];
    float4 c1 = ((const float4*)hscm)[i1];
    r.x += c1.x; r.y += c1.y; r.z += c1.z; r.w += c1.w;
    ((float4*)res1)[r4] = r;

    const float tot = block_sum256(r.x * r.x + r.y * r.y + r.z * r.z + r.w * r.w);
    const float scale = rsqrtf(tot * (1.f / (float)DM) + 1e-5f);

    float w0 = wavg[s], w1 = wavg[1024 + s], w2 = wavg[2048 + s], w3 = wavg[3072 + s];
    const float mx = fmaxf(fmaxf(w0, w1), fmaxf(w2, w3));
    w0 = __expf(w0 - mx); w1 = __expf(w1 - mx); w2 = __expf(w2 - mx); w3 = __expf(w3 - mx);
    const float inv = 1.f / (w0 + w1 + w2 + w3);
    w0 *= inv; w1 *= inv; w2 *= inv; w3 *= inv;

    const float4 a0 = ((const float4*)hstm)[i0];
    const float4 a1 = ((const float4*)hstm)[i1];
    const float4 c0 = ((const float4*)hscm)[i0];
    const float4 wn = ((const float4*)nw)[t];
    float4 o;
    o.x = w0 * a0.x + w1 * a1.x + w2 * c0.x + w3 * (r.x * scale * wn.x);
    o.y = w0 * a0.y + w1 * a1.y + w2 * c0.y + w3 * (r.y * scale * wn.y);
    o.z = w0 * a0.z + w1 * a1.z + w2 * c0.z + w3 * (r.z * scale * wn.z);
    o.w = w0 * a0.w + w1 * a1.w + w2 * c0.w + w3 * (r.w * scale * wn.w);
    ((float4*)hmix)[r4] = o;
}

__global__ __launch_bounds__(256) void rms_mix_cm_kernel(
    const float* __restrict__ res1, const float* __restrict__ outm,
    const float* __restrict__ hstm, const float* __restrict__ hscm,
    const float* __restrict__ nw, const float* __restrict__ wavg,
    float* __restrict__ res2, float* __restrict__ hmix)
{
    const int bs = blockIdx.x, b = bs >> 10, s = bs & 1023, t = threadIdx.x;
    const size_t r4 = (size_t)bs * 256 + t;
    const size_t i0 = ((size_t)(b * 2 + 0) * 1024 + s) * 256 + t;
    const size_t i1 = ((size_t)(b * 2 + 1) * 1024 + s) * 256 + t;

    float4 r  = ((const float4*)res1)[r4];
    float4 om = ((const float4*)outm)[r4];
    r.x += om.x; r.y += om.y; r.z += om.z; r.w += om.w;
    ((float4*)res2)[r4] = r;

    const float tot = block_sum256(r.x * r.x + r.y * r.y + r.z * r.z + r.w * r.w);
    const float scale = rsqrtf(tot * (1.f / (float)DM) + 1e-5f);

    float w[5];
#pragma unroll
    for (int n = 0; n < 5; n++) w[n] = wavg[n * 1024 + s];
    float mx = w[0];
#pragma unroll
    for (int n = 1; n < 5; n++) mx = fmaxf(mx, w[n]);
    float sum = 0.f;
#pragma unroll
    for (int n = 0; n < 5; n++) { w[n] = __expf(w[n] - mx); sum += w[n]; }
    const float inv = 1.f / sum;
#pragma unroll
    for (int n = 0; n < 5; n++) w[n] *= inv;

    const float4 a0 = ((const float4*)hstm)[i0];
    const float4 a1 = ((const float4*)hstm)[i1];
    const float4 c0 = ((const float4*)hscm)[i0];
    const float4 c1 = ((const float4*)hscm)[i1];
    const float4 wn = ((const float4*)nw)[t];
    float4 o;
    o.x = w[0]*a0.x + w[1]*a1.x + w[2]*(r.x*scale*wn.x) + w[3]*c0.x + w[4]*c1.x;
    o.y = w[0]*a0.y + w[1]*a1.y + w[2]*(r.y*scale*wn.y) + w[3]*c0.y + w[4]*c1.y;
    o.z = w[0]*a0.z + w[1]*a1.z + w[2]*(r.z*scale*wn.z) + w[3]*c0.z + w[4]*c1.z;
    o.w = w[0]*a0.w + w[1]*a1.w + w[2]*(r.w*scale*wn.w) + w[3]*c0.w + w[4]*c1.w;
    ((float4*)hmix)[r4] = o;
}

__global__ __launch_bounds__(256) void transpose_kernel(
    const float* __restrict__ in, float* __restrict__ out)
{
    __shared__ float tile[32][33];
    const int b = blockIdx.z;
    const int r0 = blockIdx.y * 32, c0 = blockIdx.x * 32;
    const size_t base = (size_t)b * 1024 * 1024;
#pragma unroll
    for (int i = threadIdx.y; i < 32; i += 8)
        tile[i][threadIdx.x] = in[base + (size_t)(r0 + i) * 1024 + c0 + threadIdx.x];
    __syncthreads();
#pragma unroll
    for (int i = threadIdx.y; i < 32; i += 8)
        out[base + (size_t)(c0 + i) * 1024 + r0 + threadIdx.x] = tile[threadIdx.x][i];
}

// ---------------------------------------------------------------------------
// host side
// ---------------------------------------------------------------------------
static void run_mamba(const float* x, const float* const* P, float* out,
                      float* xz, float* xh, float* dtb, float* yb, float* xdbl)
{
    const float* in_w   = P[0];
    const float* conv_w = P[1];
    const float* conv_b = P[2];
    const float* xproj  = P[3];
    const float* dt_w   = P[4];
    const float* dt_b   = P[5];
    const float* A_log  = P[6];
    const float* Dp     = P[7];
    const float* out_w  = P[8];

    gemm_mma<0><<<dim3(2 * DI_ / 256, ROWS / 128), 256, SMEM_T>>>(
        x, DM, in_w, nullptr, xz, ROWS, 2 * DI_, DM);
    conv_silu_kernel<<<(ROWS * DI_) / 256, 256>>>(xz, conv_w, conv_b, xh);
    gemm_mma<0><<<dim3(1, ROWS / 128), 256, SMEM_T>>>(
        xh, DI_, xproj, nullptr, xdbl, ROWS, XD, DI_);
    gemm_mma<1><<<dim3(DI_ / 256, ROWS / 128), 256, SMEM_T>>>(
        xdbl, XD, dt_w, dt_b, dtb, ROWS, DI_, DTR);
    scan_kernel<<<dim3(DI_ / 128, BSZ), 128>>>(dtb, xh, xdbl, xz, A_log, Dp, yb);
    gemm_mma<0><<<dim3(DM / 256, ROWS / 128), 256, SMEM_T>>>(
        yb, DI_, out_w, nullptr, out, ROWS, DM, DI_);
}

extern "C" void kernel_launch(void* const* d_in, const int* in_sizes, int n_in,
                              void* d_out, int out_size)
{
    cudaFuncSetAttribute(gemm_mma<0>, cudaFuncAttributeMaxDynamicSharedMemorySize, SMEM_T);
    cudaFuncSetAttribute(gemm_mma<1>, cudaFuncAttributeMaxDynamicSharedMemorySize, SMEM_T);

    const float* hstm     = (const float*)d_in[0];
    const float* hscm     = (const float*)d_in[1];
    const float* residual = (const float*)d_in[2];
    const float* norm_tm  = (const float*)d_in[3];
    const float* wavg_tm  = (const float*)d_in[4];

    const float *norm_cm, *wavg_cm;
    int btm;
    const int bcm = 16;
    if (in_sizes[5] == 1024) {            // dict order
        norm_cm = (const float*)d_in[5];
        wavg_cm = (const float*)d_in[6];
        btm = 7;
    } else {                              // signature order
        btm = 5;
        norm_cm = (const float*)d_in[14];
        wavg_cm = (const float*)d_in[15];
    }
    const float* P_tm[9];
    const float* P_cm[9];
    for (int i = 0; i < 9; i++) {
        P_tm[i] = (const float*)d_in[btm + i];
        P_cm[i] = (const float*)d_in[bcm + i];
    }

    float *xz, *xh, *dtb, *yb, *xdbl, *res1, *hmix, *hmixT, *outm;
    cudaGetSymbolAddress((void**)&xz,    g_xz);
    cudaGetSymbolAddress((void**)&xh,    g_xh);
    cudaGetSymbolAddress((void**)&dtb,   g_dt);
    cudaGetSymbolAddress((void**)&yb,    g_y);
    cudaGetSymbolAddress((void**)&xdbl,  g_xdbl);
    cudaGetSymbolAddress((void**)&res1,  g_res1);
    cudaGetSymbolAddress((void**)&hmix,  g_hmix);
    cudaGetSymbolAddress((void**)&hmixT, g_hmixT);
    cudaGetSymbolAddress((void**)&outm,  g_outm);

    float* dout = (float*)d_out;
    const long total = (long)BSZ * SEQ * DM;
    float* res2_out = (out_size >= 2 * total) ? (dout + total) : res1;

    // --- token-mixer path ---
    rms_mix_tm_kernel<<<ROWS, 256>>>(residual, hstm, hscm, norm_tm, wavg_tm, res1, hmix);
    run_mamba(hmix, P_tm, outm, xz, xh, dtb, yb, xdbl);

    // --- channel-mixer path ---
    rms_mix_cm_kernel<<<ROWS, 256>>>(res1, outm, hstm, hscm, norm_cm, wavg_cm, res2_out, hmix);
    transpose_kernel<<<dim3(32, 32, BSZ), dim3(32, 8)>>>(hmix, hmixT);
    run_mamba(hmixT, P_cm, outm, xz, xh, dtb, yb, xdbl);
    transpose_kernel<<<dim3(32, 32, BSZ), dim3(32, 8)>>>(outm, dout);
}